// round 1
// baseline (speedup 1.0000x reference)
#include <cuda_runtime.h>
#include <math.h>

#define FN 360
#define BGRAPH 128
#define NNODE (FN*BGRAPH)     /* 46080 */
#define NEDGE 1000000
#define CCH 128
#define TRI 64980             /* 360*361/2 */
#define D1 65364              /* TRI + 384 */
#define H1 512
#define H2 256
#define EPSV 1e-5f

// ---------------- scratch (static device allocations) ----------------
__device__ __align__(16) float g_dinv[NNODE];
__device__ __align__(16) float g_A[(size_t)BGRAPH*FN*FN];       // 66.4 MB
__device__ __align__(16) float g_h[(size_t)NNODE*CCH];
__device__ __align__(16) float g_xs1[(size_t)NNODE*CCH];
__device__ __align__(16) float g_xs2[(size_t)NNODE*CCH];
__device__ __align__(16) float g_xs3[(size_t)NNODE*CCH];
__device__ __align__(16) float g_z[(size_t)BGRAPH*D1];          // 33.5 MB
__device__ __align__(16) float g_hpool[BGRAPH*384];
__device__ __align__(16) float g_a1[BGRAPH*H1];
__device__ __align__(16) float g_a2[BGRAPH*H2];
__device__ __align__(16) float g_a3[BGRAPH*H2];

// ---------------- graph structure kernels ----------------
__global__ void k_count_deg(const int* __restrict__ dst) {
    int i = blockIdx.x*blockDim.x + threadIdx.x;
    if (i < NEDGE) atomicAdd(&g_dinv[dst[i]], 1.0f);
}
__global__ void k_make_dinv() {
    int i = blockIdx.x*blockDim.x + threadIdx.x;
    if (i < NNODE) g_dinv[i] = rsqrtf(g_dinv[i] + 1.0f);   // +1 self loop
}
__global__ void k_build_A(const int* __restrict__ src, const int* __restrict__ dst) {
    int i = blockIdx.x*blockDim.x + threadIdx.x;
    if (i >= NEDGE) return;
    int d = dst[i], s = src[i];
    int b = d / FN;
    int r = d - b*FN;
    int c = s - b*FN;
    atomicAdd(&g_A[((size_t)b*FN + r)*FN + c], g_dinv[s]*g_dinv[d]);
}
__global__ void k_add_self() {
    int i = blockIdx.x*blockDim.x + threadIdx.x;
    if (i >= NNODE) return;
    int b = i / FN, r = i - b*FN;
    g_A[((size_t)b*FN + r)*FN + r] += g_dinv[i]*g_dinv[i];
}

// ---------------- generic fp32 GEMM (128x128 tile, 8x8/thread) ----------------
// C = A[M,K] @ B[K,N] (+bias)(+tanh); blockIdx.z = batch (strides) or k-split chunk.
template<int ACT, int SPLIT>
__global__ __launch_bounds__(256)
void gemmk(const float* __restrict__ A, const float* __restrict__ Bm,
           const float* __restrict__ bias, float* __restrict__ C,
           int M, int N, int K, long sA, long sB, long sC, int kchunk)
{
    constexpr int BK = 8;
    A  += (long)blockIdx.z * sA;
    Bm += (long)blockIdx.z * sB;
    C  += (long)blockIdx.z * sC;

    int kbeg = 0, kend = K;
    if (SPLIT) { kbeg = blockIdx.z * kchunk; kend = min(K, kbeg + kchunk); }

    __shared__ float As[BK][128];
    __shared__ float Bs[BK][128];

    const int tid = threadIdx.x;
    const int tcol = tid & 15;     // 0..15
    const int trow = tid >> 4;     // 0..15
    const int rowBase = blockIdx.x * 128;
    const int colBase = blockIdx.y * 128;

    const int aRow = tid >> 1;         // 0..127
    const int aCol = (tid & 1) * 4;    // 0 or 4
    const int bRow = tid >> 5;         // 0..7
    const int bCol = (tid & 31) * 4;   // 0..124

    float acc[8][8];
    #pragma unroll
    for (int i = 0; i < 8; i++)
        #pragma unroll
        for (int j = 0; j < 8; j++) acc[i][j] = 0.f;

    for (int k0 = kbeg; k0 < kend; k0 += BK) {
        // A tile: 128 x 8 (transposed store)
        {
            int gm = rowBase + aRow;
            int gk = k0 + aCol;
            float4 v = make_float4(0.f,0.f,0.f,0.f);
            if (gm < M) {
                if (gk + 3 < kend) {
                    v = *(const float4*)(A + (long)gm*K + gk);
                } else {
                    if (gk + 0 < kend) v.x = A[(long)gm*K + gk + 0];
                    if (gk + 1 < kend) v.y = A[(long)gm*K + gk + 1];
                    if (gk + 2 < kend) v.z = A[(long)gm*K + gk + 2];
                    if (gk + 3 < kend) v.w = A[(long)gm*K + gk + 3];
                }
            }
            As[aCol+0][aRow] = v.x; As[aCol+1][aRow] = v.y;
            As[aCol+2][aRow] = v.z; As[aCol+3][aRow] = v.w;
        }
        // B tile: 8 x 128
        {
            int gk = k0 + bRow;
            int gn = colBase + bCol;
            float4 v = make_float4(0.f,0.f,0.f,0.f);
            if (gk < kend && gn < N) v = *(const float4*)(Bm + (long)gk*N + gn);
            *(float4*)&Bs[bRow][bCol] = v;
        }
        __syncthreads();
        #pragma unroll
        for (int kk = 0; kk < BK; kk++) {
            float ra[8], rb[8];
            #pragma unroll
            for (int i = 0; i < 8; i++) ra[i] = As[kk][trow*8 + i];
            #pragma unroll
            for (int j = 0; j < 8; j++) rb[j] = Bs[kk][tcol*8 + j];
            #pragma unroll
            for (int i = 0; i < 8; i++)
                #pragma unroll
                for (int j = 0; j < 8; j++)
                    acc[i][j] = fmaf(ra[i], rb[j], acc[i][j]);
        }
        __syncthreads();
    }

    #pragma unroll
    for (int i = 0; i < 8; i++) {
        int gm = rowBase + trow*8 + i;
        if (gm >= M) continue;
        #pragma unroll
        for (int j = 0; j < 8; j++) {
            int gn = colBase + tcol*8 + j;
            if (gn >= N) continue;
            float v = acc[i][j];
            if (SPLIT) {
                atomicAdd(&C[(long)gm*N + gn], v);
            } else {
                if (bias) v += bias[gn];
                if (ACT) v = tanhf(v);
                C[(long)gm*N + gn] = v;
            }
        }
    }
}

// ---------------- x0 (upper-triangular) gather + BN into z[:, 0:TRI] --------
__global__ void k_x0_bn(const float* __restrict__ x, const float* __restrict__ g,
                        const float* __restrict__ be, float* __restrict__ z)
{
    int r = blockIdx.x;               // 0..359
    int c = r + threadIdx.x;
    if (c >= FN) return;
    long j = (long)r*FN - (long)r*(r-1)/2 + (c - r);
    float s = 0.f, ss = 0.f;
    for (int b = 0; b < BGRAPH; b++) {
        float v = x[((long)(b*FN + r))*FN + c];
        s += v; ss += v*v;
    }
    float m = s * (1.f/BGRAPH);
    float var = ss * (1.f/BGRAPH) - m*m;
    float sc = rsqrtf(var + EPSV) * g[j];
    float bb = be[j];
    for (int b = 0; b < BGRAPH; b++) {
        float v = x[((long)(b*FN + r))*FN + c];
        z[(long)b*D1 + j] = (v - m)*sc + bb;
    }
}

// ---------------- per-graph mean pooling of the 3 GCN outputs ----------------
__global__ void k_pool(const float* __restrict__ x1, const float* __restrict__ x2,
                       const float* __restrict__ x3, float* __restrict__ hp)
{
    int b = blockIdx.x, k = threadIdx.x;   // 128 graphs x 128 channels
    const float* ptrs[3] = {x1, x2, x3};
    #pragma unroll
    for (int l = 0; l < 3; l++) {
        const float* base = ptrs[l] + (long)b*FN*CCH + k;
        float s = 0.f;
        for (int n = 0; n < FN; n++) s += base[(long)n*CCH];
        hp[b*384 + l*CCH + k] = s * (1.0f/FN);
    }
}

// ---------------- BN of pooled features into z[:, TRI:D1] ----------------
__global__ void k_bn_pool(const float* __restrict__ hp, const float* __restrict__ g,
                          const float* __restrict__ be, float* __restrict__ z)
{
    int j = blockIdx.x*blockDim.x + threadIdx.x;
    if (j >= 384) return;
    float s = 0.f, ss = 0.f;
    for (int b = 0; b < BGRAPH; b++) { float v = hp[b*384 + j]; s += v; ss += v*v; }
    float m = s * (1.f/BGRAPH);
    float var = ss * (1.f/BGRAPH) - m*m;
    float sc = rsqrtf(var + EPSV) * g[j];
    float bb = be[j];
    for (int b = 0; b < BGRAPH; b++)
        z[(long)b*D1 + TRI + j] = (hp[b*384 + j] - m)*sc + bb;
}

// ---------------- column BN (+bias) + ReLU, 128 rows ----------------
__global__ void k_bn_relu(const float* __restrict__ X, const float* __restrict__ bias,
                          const float* __restrict__ gam, const float* __restrict__ bet,
                          float* __restrict__ Y, int ncols)
{
    int col = blockIdx.x;
    int t = threadIdx.x;   // 0..127 = row
    float v = X[t*ncols + col] + bias[col];
    float s = v, ss = v*v;
    #pragma unroll
    for (int o = 16; o > 0; o >>= 1) {
        s  += __shfl_down_sync(0xffffffffu, s,  o);
        ss += __shfl_down_sync(0xffffffffu, ss, o);
    }
    __shared__ float ws[4], wss[4];
    __shared__ float sm, sscale;
    int wid = t >> 5, lane = t & 31;
    if (lane == 0) { ws[wid] = s; wss[wid] = ss; }
    __syncthreads();
    if (t == 0) {
        float S = ws[0]+ws[1]+ws[2]+ws[3];
        float SS = wss[0]+wss[1]+wss[2]+wss[3];
        float m = S * (1.f/BGRAPH);
        float var = SS * (1.f/BGRAPH) - m*m;
        sm = m; sscale = rsqrtf(var + EPSV);
    }
    __syncthreads();
    float o = (v - sm) * sscale * gam[col] + bet[col];
    Y[t*ncols + col] = fmaxf(o, 0.f);
}

// ---------------- final linear + log_softmax ----------------
__global__ void k_head(const float* __restrict__ a3, const float* __restrict__ W4,
                       const float* __restrict__ b4, float* __restrict__ out)
{
    int b = blockIdx.x, lane = threadIdx.x;
    float s0 = 0.f, s1 = 0.f;
    for (int i = lane; i < H2; i += 32) {
        float v = a3[b*H2 + i];
        s0 = fmaf(v, W4[i*2 + 0], s0);
        s1 = fmaf(v, W4[i*2 + 1], s1);
    }
    #pragma unroll
    for (int o = 16; o > 0; o >>= 1) {
        s0 += __shfl_down_sync(0xffffffffu, s0, o);
        s1 += __shfl_down_sync(0xffffffffu, s1, o);
    }
    if (lane == 0) {
        float l0 = s0 + b4[0], l1 = s1 + b4[1];
        float m = fmaxf(l0, l1);
        float lse = m + logf(expf(l0 - m) + expf(l1 - m));
        out[b*2 + 0] = l0 - lse;
        out[b*2 + 1] = l1 - lse;
    }
}

// ---------------- launch ----------------
extern "C" void kernel_launch(void* const* d_in, const int* in_sizes, int n_in,
                              void* d_out, int out_size)
{
    const float* x    = (const float*)d_in[0];
    const int*   esrc = (const int*)d_in[1];
    const int*   edst = (const int*)d_in[2];
    const float* Wc1  = (const float*)d_in[4];
    const float* bc1  = (const float*)d_in[5];
    const float* Wc2  = (const float*)d_in[6];
    const float* bc2  = (const float*)d_in[7];
    const float* Wc3  = (const float*)d_in[8];
    const float* bc3  = (const float*)d_in[9];
    const float* bn_g = (const float*)d_in[10];
    const float* bn_b = (const float*)d_in[11];
    const float* bnh_g= (const float*)d_in[12];
    const float* bnh_b= (const float*)d_in[13];
    const float* W1   = (const float*)d_in[14];
    const float* b1   = (const float*)d_in[15];
    const float* g1   = (const float*)d_in[16];
    const float* be1  = (const float*)d_in[17];
    const float* W2   = (const float*)d_in[18];
    const float* b2   = (const float*)d_in[19];
    const float* g2   = (const float*)d_in[20];
    const float* be2  = (const float*)d_in[21];
    const float* W3   = (const float*)d_in[22];
    const float* b3   = (const float*)d_in[23];
    const float* g3   = (const float*)d_in[24];
    const float* be3  = (const float*)d_in[25];
    const float* W4   = (const float*)d_in[26];
    const float* b4   = (const float*)d_in[27];
    float* out = (float*)d_out;

    void *pDinv, *pA, *pH, *pX1, *pX2, *pX3, *pZ, *pHp, *pA1, *pA2, *pA3;
    cudaGetSymbolAddress(&pDinv, g_dinv);
    cudaGetSymbolAddress(&pA,  g_A);
    cudaGetSymbolAddress(&pH,  g_h);
    cudaGetSymbolAddress(&pX1, g_xs1);
    cudaGetSymbolAddress(&pX2, g_xs2);
    cudaGetSymbolAddress(&pX3, g_xs3);
    cudaGetSymbolAddress(&pZ,  g_z);
    cudaGetSymbolAddress(&pHp, g_hpool);
    cudaGetSymbolAddress(&pA1, g_a1);
    cudaGetSymbolAddress(&pA2, g_a2);
    cudaGetSymbolAddress(&pA3, g_a3);

    // 1) degrees -> dinv
    cudaMemsetAsync(pDinv, 0, (size_t)NNODE*sizeof(float), 0);
    k_count_deg<<<(NEDGE+255)/256, 256>>>(edst);
    k_make_dinv<<<(NNODE+255)/256, 256>>>();

    // 2) dense normalized adjacency (shared by all 3 layers)
    cudaMemsetAsync(pA, 0, (size_t)BGRAPH*FN*FN*sizeof(float), 0);
    k_build_A<<<(NEDGE+255)/256, 256>>>(esrc, edst);
    k_add_self<<<(NNODE+255)/256, 256>>>();

    const long sAb = (long)FN*FN;      // per-graph adjacency stride
    const long sHb = (long)FN*CCH;     // per-graph feature stride

    // 3) GCN layer 1: h = x @ Wc1 ; xs1 = tanh(A @ h + bc1)
    gemmk<0,0><<<dim3(360,1,1), 256>>>(x, Wc1, nullptr, (float*)pH,
                                       NNODE, CCH, FN, 0,0,0, 0);
    gemmk<1,0><<<dim3(3,1,BGRAPH), 256>>>((const float*)pA, (const float*)pH, bc1, (float*)pX1,
                                          FN, CCH, FN, sAb, sHb, sHb, 0);
    // 4) layer 2
    gemmk<0,0><<<dim3(360,1,1), 256>>>((const float*)pX1, Wc2, nullptr, (float*)pH,
                                       NNODE, CCH, CCH, 0,0,0, 0);
    gemmk<1,0><<<dim3(3,1,BGRAPH), 256>>>((const float*)pA, (const float*)pH, bc2, (float*)pX2,
                                          FN, CCH, FN, sAb, sHb, sHb, 0);
    // 5) layer 3
    gemmk<0,0><<<dim3(360,1,1), 256>>>((const float*)pX2, Wc3, nullptr, (float*)pH,
                                       NNODE, CCH, CCH, 0,0,0, 0);
    gemmk<1,0><<<dim3(3,1,BGRAPH), 256>>>((const float*)pA, (const float*)pH, bc3, (float*)pX3,
                                          FN, CCH, FN, sAb, sHb, sHb, 0);

    // 6) z = [ BN(triu(x)) | BN(pool(xs1..3)) ]
    k_x0_bn<<<FN, 384>>>(x, bn_g, bn_b, (float*)pZ);
    k_pool<<<BGRAPH, CCH>>>((const float*)pX1, (const float*)pX2, (const float*)pX3, (float*)pHp);
    k_bn_pool<<<3, 128>>>((const float*)pHp, bnh_g, bnh_b, (float*)pZ);

    // 7) a1 = relu(BN(z @ W1 + b1))   (split-K, fp32 atomics)
    cudaMemsetAsync(pA1, 0, (size_t)BGRAPH*H1*sizeof(float), 0);
    gemmk<0,1><<<dim3(1,4,64), 256>>>((const float*)pZ, W1, nullptr, (float*)pA1,
                                      BGRAPH, H1, D1, 0,0,0, 1024);
    k_bn_relu<<<H1, 128>>>((const float*)pA1, b1, g1, be1, (float*)pA1, H1);

    // 8) a2 = relu(BN(a1 @ W2 + b2))
    gemmk<0,0><<<dim3(1,2,1), 256>>>((const float*)pA1, W2, nullptr, (float*)pA2,
                                     BGRAPH, H2, H1, 0,0,0, 0);
    k_bn_relu<<<H2, 128>>>((const float*)pA2, b2, g2, be2, (float*)pA2, H2);

    // 9) a3 = relu(BN(a2 @ W3 + b3))
    gemmk<0,0><<<dim3(1,2,1), 256>>>((const float*)pA2, W3, nullptr, (float*)pA3,
                                     BGRAPH, H2, H2, 0,0,0, 0);
    k_bn_relu<<<H2, 128>>>((const float*)pA3, b3, g3, be3, (float*)pA3, H2);

    // 10) logits + log_softmax
    k_head<<<BGRAPH, 32>>>((const float*)pA3, W4, b4, out);
}

// round 2
// speedup vs baseline: 1.8881x; 1.8881x over previous
#include <cuda_runtime.h>
#include <math.h>
#include <stdint.h>

#define FN 360
#define BGRAPH 128
#define NNODE (FN*BGRAPH)     /* 46080 */
#define NEDGE 1000000
#define CCH 128
#define TRI 64980             /* 360*361/2 */
#define D1 65364              /* TRI + 384 */
#define H1 512
#define H2 256
#define EPSV 1e-5f
#define PADK 136

// ---------------- scratch (static device allocations) ----------------
__device__ __align__(16) float g_dinv[NNODE];
__device__ __align__(16) float g_A[(size_t)BGRAPH*FN*FN];       // 66.4 MB
__device__ __align__(16) float g_h[(size_t)NNODE*CCH];
__device__ __align__(16) float g_xs1[(size_t)NNODE*CCH];
__device__ __align__(16) float g_xs2[(size_t)NNODE*CCH];
__device__ __align__(16) float g_xs3[(size_t)NNODE*CCH];
__device__ __align__(16) float g_z[(size_t)BGRAPH*D1];          // 33.5 MB
__device__ __align__(16) float g_hpool[BGRAPH*384];
__device__ __align__(16) float g_a1[BGRAPH*H1];
__device__ __align__(16) float g_a2[BGRAPH*H2];
__device__ __align__(16) float g_a3[BGRAPH*H2];

// ---------------- graph structure kernels ----------------
__global__ void k_count_deg(const int* __restrict__ dst) {
    int i = blockIdx.x*blockDim.x + threadIdx.x;
    if (i < NEDGE) atomicAdd(&g_dinv[dst[i]], 1.0f);
}
__global__ void k_make_dinv() {
    int i = blockIdx.x*blockDim.x + threadIdx.x;
    if (i < NNODE) g_dinv[i] = rsqrtf(g_dinv[i] + 1.0f);   // +1 self loop
}
__global__ void k_build_A(const int* __restrict__ src, const int* __restrict__ dst) {
    int i = blockIdx.x*blockDim.x + threadIdx.x;
    if (i >= NEDGE) return;
    int d = dst[i], s = src[i];
    int b = d / FN;
    int r = d - b*FN;
    int c = s - b*FN;
    atomicAdd(&g_A[((size_t)b*FN + r)*FN + c], g_dinv[s]*g_dinv[d]);
}
__global__ void k_add_self() {
    int i = blockIdx.x*blockDim.x + threadIdx.x;
    if (i >= NNODE) return;
    int b = i / FN, r = i - b*FN;
    g_A[((size_t)b*FN + r)*FN + r] += g_dinv[i]*g_dinv[i];
}

// ---------------- tf32 tensor-core GEMM ----------------
// C = A[M,K] @ B[K,N]; 128x128 block tile, BK=16, 8 warps (2x4), each warp 64x32.
// ACT: add bias + tanh in epilogue. SPLIT: k-split chunks along blockIdx.z with atomicAdd.
// Otherwise blockIdx.z = batch index with strides sA/sB/sC.

__device__ __forceinline__ uint32_t f2tf(float f) {
    uint32_t u; asm("cvt.rna.tf32.f32 %0, %1;" : "=r"(u) : "f"(f)); return u;
}
__device__ __forceinline__ void mma8(float* c, const uint32_t* a, const uint32_t* b) {
    asm volatile("mma.sync.aligned.m16n8k8.row.col.f32.tf32.tf32.f32 "
        "{%0,%1,%2,%3}, {%4,%5,%6,%7}, {%8,%9}, {%0,%1,%2,%3};"
        : "+f"(c[0]), "+f"(c[1]), "+f"(c[2]), "+f"(c[3])
        : "r"(a[0]), "r"(a[1]), "r"(a[2]), "r"(a[3]), "r"(b[0]), "r"(b[1]));
}

template<int ACT, int SPLIT>
__global__ __launch_bounds__(256)
void mmak(const float* __restrict__ A, const float* __restrict__ Bm,
          const float* __restrict__ bias, float* __restrict__ C,
          int M, int N, int K, long sA, long sB, long sC, int kchunk)
{
    if (!SPLIT) {
        A  += (long)blockIdx.z * sA;
        Bm += (long)blockIdx.z * sB;
        C  += (long)blockIdx.z * sC;
    }
    int kbeg = 0, kend = K;
    if (SPLIT) { kbeg = blockIdx.z * kchunk; kend = min(K, kbeg + kchunk); }

    __shared__ uint32_t As[16][PADK];   // [k][m]
    __shared__ uint32_t Bs[16][PADK];   // [k][n]

    const int tid  = threadIdx.x;
    const int lane = tid & 31;
    const int w    = tid >> 5;
    const int wm   = (w & 1) * 64;
    const int wn   = (w >> 1) * 32;
    const int g    = lane >> 2;     // 0..7
    const int kt   = lane & 3;      // 0..3
    const int rowBase = blockIdx.x * 128;
    const int colBase = blockIdx.y * 128;

    const int aRow = tid >> 1;              // 0..127
    const int aCol = (tid & 1) * 8;         // 0 or 8
    const int bRow = tid >> 4;              // 0..15
    const int bCol = (tid & 15) * 8;        // 0..120

    float acc[4][4][4];
    #pragma unroll
    for (int mi = 0; mi < 4; mi++)
        #pragma unroll
        for (int nj = 0; nj < 4; nj++)
            #pragma unroll
            for (int r = 0; r < 4; r++) acc[mi][nj][r] = 0.f;

    for (int k0 = kbeg; k0 < kend; k0 += 16) {
        // --- load A tile 128x16 -> As[k][m] (tf32) ---
        {
            int gm = aRow + rowBase;
            #pragma unroll
            for (int h = 0; h < 2; h++) {
                int gk = k0 + aCol + h*4;
                float4 v = make_float4(0.f,0.f,0.f,0.f);
                if (gm < M) {
                    if (gk + 3 < kend) {
                        v = *(const float4*)(A + (long)gm*K + gk);
                    } else {
                        if (gk+0 < kend) v.x = A[(long)gm*K + gk + 0];
                        if (gk+1 < kend) v.y = A[(long)gm*K + gk + 1];
                        if (gk+2 < kend) v.z = A[(long)gm*K + gk + 2];
                        if (gk+3 < kend) v.w = A[(long)gm*K + gk + 3];
                    }
                }
                As[aCol+h*4+0][aRow] = f2tf(v.x);
                As[aCol+h*4+1][aRow] = f2tf(v.y);
                As[aCol+h*4+2][aRow] = f2tf(v.z);
                As[aCol+h*4+3][aRow] = f2tf(v.w);
            }
        }
        // --- load B tile 16x128 -> Bs[k][n] (tf32) ---
        {
            int gk = k0 + bRow;
            #pragma unroll
            for (int h = 0; h < 2; h++) {
                int gn = colBase + bCol + h*4;
                float4 v = make_float4(0.f,0.f,0.f,0.f);
                if (gk < kend) v = *(const float4*)(Bm + (long)gk*N + gn);
                Bs[bRow][bCol+h*4+0] = f2tf(v.x);
                Bs[bRow][bCol+h*4+1] = f2tf(v.y);
                Bs[bRow][bCol+h*4+2] = f2tf(v.z);
                Bs[bRow][bCol+h*4+3] = f2tf(v.w);
            }
        }
        __syncthreads();
        #pragma unroll
        for (int ks = 0; ks < 2; ks++) {
            uint32_t af[4][4], bf[4][2];
            #pragma unroll
            for (int mi = 0; mi < 4; mi++) {
                int m = wm + mi*16;
                af[mi][0] = As[ks*8 + kt    ][m + g    ];
                af[mi][1] = As[ks*8 + kt    ][m + g + 8];
                af[mi][2] = As[ks*8 + kt + 4][m + g    ];
                af[mi][3] = As[ks*8 + kt + 4][m + g + 8];
            }
            #pragma unroll
            for (int nj = 0; nj < 4; nj++) {
                int n = wn + nj*8;
                bf[nj][0] = Bs[ks*8 + kt    ][n + g];
                bf[nj][1] = Bs[ks*8 + kt + 4][n + g];
            }
            #pragma unroll
            for (int mi = 0; mi < 4; mi++)
                #pragma unroll
                for (int nj = 0; nj < 4; nj++)
                    mma8(acc[mi][nj], af[mi], bf[nj]);
        }
        __syncthreads();
    }

    // --- epilogue ---
    #pragma unroll
    for (int mi = 0; mi < 4; mi++) {
        #pragma unroll
        for (int nj = 0; nj < 4; nj++) {
            #pragma unroll
            for (int r = 0; r < 4; r++) {
                int gm = rowBase + wm + mi*16 + g + (r >> 1)*8;
                int gn = colBase + wn + nj*8 + kt*2 + (r & 1);
                if (gm < M && gn < N) {
                    float v = acc[mi][nj][r];
                    if (SPLIT) {
                        atomicAdd(&C[(long)gm*N + gn], v);
                    } else {
                        if (bias) v += bias[gn];
                        if (ACT) v = tanhf(v);
                        C[(long)gm*N + gn] = v;
                    }
                }
            }
        }
    }
}

// ---------------- x0 (upper-triangular) gather + BN into z[:, 0:TRI] --------
__global__ void k_x0_bn(const float* __restrict__ x, const float* __restrict__ g,
                        const float* __restrict__ be, float* __restrict__ z)
{
    int r = blockIdx.x;               // 0..359
    int c = r + threadIdx.x;
    if (c >= FN) return;
    long j = (long)r*FN - (long)r*(r-1)/2 + (c - r);
    float s = 0.f, ss = 0.f;
    for (int b = 0; b < BGRAPH; b++) {
        float v = x[((long)(b*FN + r))*FN + c];
        s += v; ss += v*v;
    }
    float m = s * (1.f/BGRAPH);
    float var = ss * (1.f/BGRAPH) - m*m;
    float sc = rsqrtf(var + EPSV) * g[j];
    float bb = be[j];
    for (int b = 0; b < BGRAPH; b++) {
        float v = x[((long)(b*FN + r))*FN + c];
        z[(long)b*D1 + j] = (v - m)*sc + bb;
    }
}

// ---------------- per-graph mean pooling of the 3 GCN outputs ----------------
__global__ void k_pool(const float* __restrict__ x1, const float* __restrict__ x2,
                       const float* __restrict__ x3, float* __restrict__ hp)
{
    int b = blockIdx.x, k = threadIdx.x;   // 128 graphs x 128 channels
    const float* ptrs[3] = {x1, x2, x3};
    #pragma unroll
    for (int l = 0; l < 3; l++) {
        const float* base = ptrs[l] + (long)b*FN*CCH + k;
        float s = 0.f;
        for (int n = 0; n < FN; n++) s += base[(long)n*CCH];
        hp[b*384 + l*CCH + k] = s * (1.0f/FN);
    }
}

// ---------------- BN of pooled features into z[:, TRI:D1] ----------------
__global__ void k_bn_pool(const float* __restrict__ hp, const float* __restrict__ g,
                          const float* __restrict__ be, float* __restrict__ z)
{
    int j = blockIdx.x*blockDim.x + threadIdx.x;
    if (j >= 384) return;
    float s = 0.f, ss = 0.f;
    for (int b = 0; b < BGRAPH; b++) { float v = hp[b*384 + j]; s += v; ss += v*v; }
    float m = s * (1.f/BGRAPH);
    float var = ss * (1.f/BGRAPH) - m*m;
    float sc = rsqrtf(var + EPSV) * g[j];
    float bb = be[j];
    for (int b = 0; b < BGRAPH; b++)
        z[(long)b*D1 + TRI + j] = (hp[b*384 + j] - m)*sc + bb;
}

// ---------------- column BN (+bias) + ReLU, 128 rows ----------------
__global__ void k_bn_relu(const float* __restrict__ X, const float* __restrict__ bias,
                          const float* __restrict__ gam, const float* __restrict__ bet,
                          float* __restrict__ Y, int ncols)
{
    int col = blockIdx.x;
    int t = threadIdx.x;   // 0..127 = row
    float v = X[t*ncols + col] + bias[col];
    float s = v, ss = v*v;
    #pragma unroll
    for (int o = 16; o > 0; o >>= 1) {
        s  += __shfl_down_sync(0xffffffffu, s,  o);
        ss += __shfl_down_sync(0xffffffffu, ss, o);
    }
    __shared__ float ws[4], wss[4];
    __shared__ float sm, sscale;
    int wid = t >> 5, lane = t & 31;
    if (lane == 0) { ws[wid] = s; wss[wid] = ss; }
    __syncthreads();
    if (t == 0) {
        float S = ws[0]+ws[1]+ws[2]+ws[3];
        float SS = wss[0]+wss[1]+wss[2]+wss[3];
        float m = S * (1.f/BGRAPH);
        float var = SS * (1.f/BGRAPH) - m*m;
        sm = m; sscale = rsqrtf(var + EPSV);
    }
    __syncthreads();
    float o = (v - sm) * sscale * gam[col] + bet[col];
    Y[t*ncols + col] = fmaxf(o, 0.f);
}

// ---------------- final linear + log_softmax ----------------
__global__ void k_head(const float* __restrict__ a3, const float* __restrict__ W4,
                       const float* __restrict__ b4, float* __restrict__ out)
{
    int b = blockIdx.x, lane = threadIdx.x;
    float s0 = 0.f, s1 = 0.f;
    for (int i = lane; i < H2; i += 32) {
        float v = a3[b*H2 + i];
        s0 = fmaf(v, W4[i*2 + 0], s0);
        s1 = fmaf(v, W4[i*2 + 1], s1);
    }
    #pragma unroll
    for (int o = 16; o > 0; o >>= 1) {
        s0 += __shfl_down_sync(0xffffffffu, s0, o);
        s1 += __shfl_down_sync(0xffffffffu, s1, o);
    }
    if (lane == 0) {
        float l0 = s0 + b4[0], l1 = s1 + b4[1];
        float m = fmaxf(l0, l1);
        float lse = m + logf(expf(l0 - m) + expf(l1 - m));
        out[b*2 + 0] = l0 - lse;
        out[b*2 + 1] = l1 - lse;
    }
}

// ---------------- launch ----------------
extern "C" void kernel_launch(void* const* d_in, const int* in_sizes, int n_in,
                              void* d_out, int out_size)
{
    const float* x    = (const float*)d_in[0];
    const int*   esrc = (const int*)d_in[1];
    const int*   edst = (const int*)d_in[2];
    const float* Wc1  = (const float*)d_in[4];
    const float* bc1  = (const float*)d_in[5];
    const float* Wc2  = (const float*)d_in[6];
    const float* bc2  = (const float*)d_in[7];
    const float* Wc3  = (const float*)d_in[8];
    const float* bc3  = (const float*)d_in[9];
    const float* bn_g = (const float*)d_in[10];
    const float* bn_b = (const float*)d_in[11];
    const float* bnh_g= (const float*)d_in[12];
    const float* bnh_b= (const float*)d_in[13];
    const float* W1   = (const float*)d_in[14];
    const float* b1   = (const float*)d_in[15];
    const float* g1   = (const float*)d_in[16];
    const float* be1  = (const float*)d_in[17];
    const float* W2   = (const float*)d_in[18];
    const float* b2   = (const float*)d_in[19];
    const float* g2   = (const float*)d_in[20];
    const float* be2  = (const float*)d_in[21];
    const float* W3   = (const float*)d_in[22];
    const float* b3   = (const float*)d_in[23];
    const float* g3   = (const float*)d_in[24];
    const float* be3  = (const float*)d_in[25];
    const float* W4   = (const float*)d_in[26];
    const float* b4   = (const float*)d_in[27];
    float* out = (float*)d_out;

    void *pDinv, *pA, *pH, *pX1, *pX2, *pX3, *pZ, *pHp, *pA1, *pA2, *pA3;
    cudaGetSymbolAddress(&pDinv, g_dinv);
    cudaGetSymbolAddress(&pA,  g_A);
    cudaGetSymbolAddress(&pH,  g_h);
    cudaGetSymbolAddress(&pX1, g_xs1);
    cudaGetSymbolAddress(&pX2, g_xs2);
    cudaGetSymbolAddress(&pX3, g_xs3);
    cudaGetSymbolAddress(&pZ,  g_z);
    cudaGetSymbolAddress(&pHp, g_hpool);
    cudaGetSymbolAddress(&pA1, g_a1);
    cudaGetSymbolAddress(&pA2, g_a2);
    cudaGetSymbolAddress(&pA3, g_a3);

    // 1) degrees -> dinv
    cudaMemsetAsync(pDinv, 0, (size_t)NNODE*sizeof(float), 0);
    k_count_deg<<<(NEDGE+255)/256, 256>>>(edst);
    k_make_dinv<<<(NNODE+255)/256, 256>>>();

    // 2) dense normalized adjacency (shared by all 3 layers)
    cudaMemsetAsync(pA, 0, (size_t)BGRAPH*FN*FN*sizeof(float), 0);
    k_build_A<<<(NEDGE+255)/256, 256>>>(esrc, edst);
    k_add_self<<<(NNODE+255)/256, 256>>>();

    const long sAb = (long)FN*FN;      // per-graph adjacency stride
    const long sHb = (long)FN*CCH;     // per-graph feature stride

    // 3) GCN layer 1: h = x @ Wc1 ; xs1 = tanh(A @ h + bc1)
    mmak<0,0><<<dim3(360,1,1), 256>>>(x, Wc1, nullptr, (float*)pH,
                                      NNODE, CCH, FN, 0,0,0, 0);
    mmak<1,0><<<dim3(3,1,BGRAPH), 256>>>((const float*)pA, (const float*)pH, bc1, (float*)pX1,
                                         FN, CCH, FN, sAb, sHb, sHb, 0);
    // 4) layer 2
    mmak<0,0><<<dim3(360,1,1), 256>>>((const float*)pX1, Wc2, nullptr, (float*)pH,
                                      NNODE, CCH, CCH, 0,0,0, 0);
    mmak<1,0><<<dim3(3,1,BGRAPH), 256>>>((const float*)pA, (const float*)pH, bc2, (float*)pX2,
                                         FN, CCH, FN, sAb, sHb, sHb, 0);
    // 5) layer 3
    mmak<0,0><<<dim3(360,1,1), 256>>>((const float*)pX2, Wc3, nullptr, (float*)pH,
                                      NNODE, CCH, CCH, 0,0,0, 0);
    mmak<1,0><<<dim3(3,1,BGRAPH), 256>>>((const float*)pA, (const float*)pH, bc3, (float*)pX3,
                                         FN, CCH, FN, sAb, sHb, sHb, 0);

    // 6) z = [ BN(triu(x)) | BN(pool(xs1..3)) ]
    k_x0_bn<<<FN, 384>>>(x, bn_g, bn_b, (float*)pZ);
    k_pool<<<BGRAPH, CCH>>>((const float*)pX1, (const float*)pX2, (const float*)pX3, (float*)pHp);
    k_bn_pool<<<3, 128>>>((const float*)pHp, bnh_g, bnh_b, (float*)pZ);

    // 7) a1 = relu(BN(z @ W1 + b1))   (tf32 split-K, fp32 atomics)
    cudaMemsetAsync(pA1, 0, (size_t)BGRAPH*H1*sizeof(float), 0);
    mmak<0,1><<<dim3(1,4,64), 256>>>((const float*)pZ, W1, nullptr, (float*)pA1,
                                     BGRAPH, H1, D1, 0,0,0, 1024);
    k_bn_relu<<<H1, 128>>>((const float*)pA1, b1, g1, be1, (float*)pA1, H1);

    // 8) a2 = relu(BN(a1 @ W2 + b2))
    mmak<0,0><<<dim3(1,2,1), 256>>>((const float*)pA1, W2, nullptr, (float*)pA2,
                                    BGRAPH, H2, H1, 0,0,0, 0);
    k_bn_relu<<<H2, 128>>>((const float*)pA2, b2, g2, be2, (float*)pA2, H2);

    // 9) a3 = relu(BN(a2 @ W3 + b3))
    mmak<0,0><<<dim3(1,2,1), 256>>>((const float*)pA2, W3, nullptr, (float*)pA3,
                                    BGRAPH, H2, H2, 0,0,0, 0);
    k_bn_relu<<<H2, 128>>>((const float*)pA3, b3, g3, be3, (float*)pA3, H2);

    // 10) logits + log_softmax
    k_head<<<BGRAPH, 32>>>((const float*)pA3, W4, b4, out);
}

// round 3
// speedup vs baseline: 2.3100x; 1.2235x over previous
#include <cuda_runtime.h>
#include <math.h>
#include <stdint.h>

#define FN 360
#define BGRAPH 128
#define NNODE (FN*BGRAPH)     /* 46080 */
#define NEDGE 1000000
#define CCH 128
#define TRI 64980             /* 360*361/2 */
#define D1 65364              /* TRI + 384 */
#define H1 512
#define H2 256
#define EPSV 1e-5f
#define PADK 136

// ---------------- scratch (static device allocations) ----------------
__device__ __align__(16) float g_dinv[NNODE];
__device__ __align__(16) float g_A[(size_t)BGRAPH*FN*FN];       // 66.4 MB
__device__ __align__(16) float g_h[(size_t)NNODE*CCH];
__device__ __align__(16) float g_xs1[(size_t)NNODE*CCH];
__device__ __align__(16) float g_xs2[(size_t)NNODE*CCH];
__device__ __align__(16) float g_xs3[(size_t)NNODE*CCH];
__device__ __align__(16) float g_z[(size_t)BGRAPH*D1];          // 33.5 MB
__device__ __align__(16) float g_hpool[BGRAPH*384];
__device__ __align__(16) float g_a1[BGRAPH*H1];
__device__ __align__(16) float g_a2[BGRAPH*H2];
__device__ __align__(16) float g_a3[BGRAPH*H2];

// ---------------- graph structure kernels ----------------
__global__ void k_count_deg(const int* __restrict__ dst) {
    int i = blockIdx.x*blockDim.x + threadIdx.x;
    if (i < NEDGE) atomicAdd(&g_dinv[dst[i]], 1.0f);
}
__global__ void k_make_dinv() {
    int i = blockIdx.x*blockDim.x + threadIdx.x;
    if (i < NNODE) g_dinv[i] = rsqrtf(g_dinv[i] + 1.0f);   // +1 self loop
}
__global__ void k_build_A(const int* __restrict__ src, const int* __restrict__ dst) {
    int i = blockIdx.x*blockDim.x + threadIdx.x;
    if (i >= NEDGE) return;
    int d = dst[i], s = src[i];
    int b = d / FN;
    int r = d - b*FN;
    int c = s - b*FN;
    atomicAdd(&g_A[((size_t)b*FN + r)*FN + c], g_dinv[s]*g_dinv[d]);
}
__global__ void k_add_self() {
    int i = blockIdx.x*blockDim.x + threadIdx.x;
    if (i >= NNODE) return;
    int b = i / FN, r = i - b*FN;
    g_A[((size_t)b*FN + r)*FN + r] += g_dinv[i]*g_dinv[i];
}

// ---------------- helpers ----------------
__device__ __forceinline__ uint32_t f2tf(float f) {
    uint32_t u; asm("cvt.rna.tf32.f32 %0, %1;" : "=r"(u) : "f"(f)); return u;
}
__device__ __forceinline__ void mma8(float* c, const uint32_t* a, const uint32_t* b) {
    asm volatile("mma.sync.aligned.m16n8k8.row.col.f32.tf32.tf32.f32 "
        "{%0,%1,%2,%3}, {%4,%5,%6,%7}, {%8,%9}, {%0,%1,%2,%3};"
        : "+f"(c[0]), "+f"(c[1]), "+f"(c[2]), "+f"(c[3])
        : "r"(a[0]), "r"(a[1]), "r"(a[2]), "r"(a[3]), "r"(b[0]), "r"(b[1]));
}
__device__ __forceinline__ float fast_tanh(float x) {
    // tanh(x) = 1 - 2/(exp(2x)+1); exact identity, __expf + fast divide.
    float e = __expf(2.0f * x);
    return 1.0f - __fdividef(2.0f, e + 1.0f);
}

// ---------------- tf32 tensor-core GEMM, double-buffered ----------------
// C = A[M,K] @ B[K,N]; 128x128 block tile, BK=16, 8 warps (2x4), warp tile 64x32.
// ACT: bias + tanh. SPLIT: k-split along blockIdx.z with atomicAdd epilogue.
// Otherwise blockIdx.z = batch index with strides sA/sB/sC.
template<int ACT, int SPLIT>
__global__ __launch_bounds__(256)
void mmak(const float* __restrict__ A, const float* __restrict__ Bm,
          const float* __restrict__ bias, float* __restrict__ C,
          int M, int N, int K, long sA, long sB, long sC, int kchunk)
{
    if (!SPLIT) {
        A  += (long)blockIdx.z * sA;
        Bm += (long)blockIdx.z * sB;
        C  += (long)blockIdx.z * sC;
    }
    int kbeg = 0, kend = K;
    if (SPLIT) { kbeg = blockIdx.z * kchunk; kend = min(K, kbeg + kchunk); }

    __shared__ uint32_t As[2][16][PADK];   // [buf][k][m]
    __shared__ uint32_t Bs[2][16][PADK];   // [buf][k][n]

    const int tid  = threadIdx.x;
    const int lane = tid & 31;
    const int w    = tid >> 5;
    const int wm   = (w & 1) * 64;
    const int wn   = (w >> 1) * 32;
    const int g    = lane >> 2;     // 0..7
    const int kt   = lane & 3;      // 0..3
    const int rowBase = blockIdx.x * 128;
    const int colBase = blockIdx.y * 128;

    const int aRow = tid >> 1;              // 0..127
    const int aCol = (tid & 1) * 8;         // 0 or 8
    const int bRow = tid >> 4;              // 0..15
    const int bCol = (tid & 15) * 8;        // 0..120

    float acc[4][4][4];
    #pragma unroll
    for (int mi = 0; mi < 4; mi++)
        #pragma unroll
        for (int nj = 0; nj < 4; nj++)
            #pragma unroll
            for (int r = 0; r < 4; r++) acc[mi][nj][r] = 0.f;

    const int gmA = rowBase + aRow;
    float4 pa[2], pb[2];

    // ---- tile loaders (global -> regs) ----
    auto loadTiles = [&](int k0) {
        #pragma unroll
        for (int h = 0; h < 2; h++) {
            int gk = k0 + aCol + h*4;
            float4 v = make_float4(0.f,0.f,0.f,0.f);
            if (gmA < M) {
                if (gk + 3 < kend) {
                    v = *(const float4*)(A + (long)gmA*K + gk);
                } else {
                    if (gk+0 < kend) v.x = A[(long)gmA*K + gk + 0];
                    if (gk+1 < kend) v.y = A[(long)gmA*K + gk + 1];
                    if (gk+2 < kend) v.z = A[(long)gmA*K + gk + 2];
                    if (gk+3 < kend) v.w = A[(long)gmA*K + gk + 3];
                }
            }
            pa[h] = v;
        }
        int gk = k0 + bRow;
        #pragma unroll
        for (int h = 0; h < 2; h++) {
            int gn = colBase + bCol + h*4;
            float4 v = make_float4(0.f,0.f,0.f,0.f);
            if (gk < kend && gn < N) v = *(const float4*)(Bm + (long)gk*N + gn);
            pb[h] = v;
        }
    };
    // ---- regs -> smem (with tf32 convert) ----
    auto storeTiles = [&](int buf) {
        #pragma unroll
        for (int h = 0; h < 2; h++) {
            As[buf][aCol+h*4+0][aRow] = f2tf(pa[h].x);
            As[buf][aCol+h*4+1][aRow] = f2tf(pa[h].y);
            As[buf][aCol+h*4+2][aRow] = f2tf(pa[h].z);
            As[buf][aCol+h*4+3][aRow] = f2tf(pa[h].w);
            Bs[buf][bRow][bCol+h*4+0] = f2tf(pb[h].x);
            Bs[buf][bRow][bCol+h*4+1] = f2tf(pb[h].y);
            Bs[buf][bRow][bCol+h*4+2] = f2tf(pb[h].z);
            Bs[buf][bRow][bCol+h*4+3] = f2tf(pb[h].w);
        }
    };
    // ---- compute one 16-deep k-tile from smem ----
    auto compute = [&](int buf) {
        #pragma unroll
        for (int ks = 0; ks < 2; ks++) {
            uint32_t af[4][4], bf[4][2];
            #pragma unroll
            for (int mi = 0; mi < 4; mi++) {
                int m = wm + mi*16;
                af[mi][0] = As[buf][ks*8 + kt    ][m + g    ];
                af[mi][1] = As[buf][ks*8 + kt    ][m + g + 8];
                af[mi][2] = As[buf][ks*8 + kt + 4][m + g    ];
                af[mi][3] = As[buf][ks*8 + kt + 4][m + g + 8];
            }
            #pragma unroll
            for (int nj = 0; nj < 4; nj++) {
                int n = wn + nj*8;
                bf[nj][0] = Bs[buf][ks*8 + kt    ][n + g];
                bf[nj][1] = Bs[buf][ks*8 + kt + 4][n + g];
            }
            #pragma unroll
            for (int mi = 0; mi < 4; mi++)
                #pragma unroll
                for (int nj = 0; nj < 4; nj++)
                    mma8(acc[mi][nj], af[mi], bf[nj]);
        }
    };

    const int nIter = (kend - kbeg + 15) >> 4;
    loadTiles(kbeg);
    storeTiles(0);
    __syncthreads();
    for (int t = 1; t < nIter; t++) {
        loadTiles(kbeg + t*16);     // LDG in flight during compute below
        compute((t-1) & 1);
        storeTiles(t & 1);
        __syncthreads();
    }
    compute((nIter-1) & 1);

    // --- epilogue ---
    #pragma unroll
    for (int mi = 0; mi < 4; mi++) {
        #pragma unroll
        for (int nj = 0; nj < 4; nj++) {
            #pragma unroll
            for (int r = 0; r < 4; r++) {
                int gm = rowBase + wm + mi*16 + g + (r >> 1)*8;
                int gn = colBase + wn + nj*8 + kt*2 + (r & 1);
                if (gm < M && gn < N) {
                    float v = acc[mi][nj][r];
                    if (SPLIT) {
                        atomicAdd(&C[(long)gm*N + gn], v);
                    } else {
                        if (bias) v += bias[gn];
                        if (ACT) v = fast_tanh(v);
                        C[(long)gm*N + gn] = v;
                    }
                }
            }
        }
    }
}

// ---------------- x0 (upper-triangular) gather + BN into z[:, 0:TRI] --------
__global__ void k_x0_bn(const float* __restrict__ x, const float* __restrict__ g,
                        const float* __restrict__ be, float* __restrict__ z)
{
    int r = blockIdx.x;               // 0..359
    int c = r + threadIdx.x;
    if (c >= FN) return;
    long j = (long)r*FN - (long)r*(r-1)/2 + (c - r);
    float s = 0.f, ss = 0.f;
    for (int b = 0; b < BGRAPH; b++) {
        float v = x[((long)(b*FN + r))*FN + c];
        s += v; ss += v*v;
    }
    float m = s * (1.f/BGRAPH);
    float var = ss * (1.f/BGRAPH) - m*m;
    float sc = rsqrtf(var + EPSV) * g[j];
    float bb = be[j];
    for (int b = 0; b < BGRAPH; b++) {
        float v = x[((long)(b*FN + r))*FN + c];
        z[(long)b*D1 + j] = (v - m)*sc + bb;
    }
}

// ---------------- per-graph mean pooling of the 3 GCN outputs ----------------
__global__ void k_pool(const float* __restrict__ x1, const float* __restrict__ x2,
                       const float* __restrict__ x3, float* __restrict__ hp)
{
    int b = blockIdx.x, l = blockIdx.y, k = threadIdx.x;
    const float* base = (l == 0 ? x1 : l == 1 ? x2 : x3) + (long)b*FN*CCH + k;
    float s0 = 0.f, s1 = 0.f, s2 = 0.f, s3 = 0.f;
    #pragma unroll 1
    for (int n = 0; n < FN; n += 4) {
        s0 += base[(long)(n+0)*CCH];
        s1 += base[(long)(n+1)*CCH];
        s2 += base[(long)(n+2)*CCH];
        s3 += base[(long)(n+3)*CCH];
    }
    hp[b*384 + l*CCH + k] = (s0+s1+s2+s3) * (1.0f/FN);
}

// ---------------- BN of pooled features into z[:, TRI:D1] ----------------
__global__ void k_bn_pool(const float* __restrict__ hp, const float* __restrict__ g,
                          const float* __restrict__ be, float* __restrict__ z)
{
    int j = blockIdx.x*blockDim.x + threadIdx.x;
    if (j >= 384) return;
    float s = 0.f, ss = 0.f;
    for (int b = 0; b < BGRAPH; b++) { float v = hp[b*384 + j]; s += v; ss += v*v; }
    float m = s * (1.f/BGRAPH);
    float var = ss * (1.f/BGRAPH) - m*m;
    float sc = rsqrtf(var + EPSV) * g[j];
    float bb = be[j];
    for (int b = 0; b < BGRAPH; b++)
        z[(long)b*D1 + TRI + j] = (hp[b*384 + j] - m)*sc + bb;
}

// ---------------- column BN (+bias) + ReLU, 128 rows ----------------
__global__ void k_bn_relu(const float* __restrict__ X, const float* __restrict__ bias,
                          const float* __restrict__ gam, const float* __restrict__ bet,
                          float* __restrict__ Y, int ncols)
{
    int col = blockIdx.x;
    int t = threadIdx.x;   // 0..127 = row
    float v = X[t*ncols + col] + bias[col];
    float s = v, ss = v*v;
    #pragma unroll
    for (int o = 16; o > 0; o >>= 1) {
        s  += __shfl_down_sync(0xffffffffu, s,  o);
        ss += __shfl_down_sync(0xffffffffu, ss, o);
    }
    __shared__ float ws[4], wss[4];
    __shared__ float sm, sscale;
    int wid = t >> 5, lane = t & 31;
    if (lane == 0) { ws[wid] = s; wss[wid] = ss; }
    __syncthreads();
    if (t == 0) {
        float S = ws[0]+ws[1]+ws[2]+ws[3];
        float SS = wss[0]+wss[1]+wss[2]+wss[3];
        float m = S * (1.f/BGRAPH);
        float var = SS * (1.f/BGRAPH) - m*m;
        sm = m; sscale = rsqrtf(var + EPSV);
    }
    __syncthreads();
    float o = (v - sm) * sscale * gam[col] + bet[col];
    Y[t*ncols + col] = fmaxf(o, 0.f);
}

// ---------------- final linear + log_softmax ----------------
__global__ void k_head(const float* __restrict__ a3, const float* __restrict__ W4,
                       const float* __restrict__ b4, float* __restrict__ out)
{
    int b = blockIdx.x, lane = threadIdx.x;
    float s0 = 0.f, s1 = 0.f;
    for (int i = lane; i < H2; i += 32) {
        float v = a3[b*H2 + i];
        s0 = fmaf(v, W4[i*2 + 0], s0);
        s1 = fmaf(v, W4[i*2 + 1], s1);
    }
    #pragma unroll
    for (int o = 16; o > 0; o >>= 1) {
        s0 += __shfl_down_sync(0xffffffffu, s0, o);
        s1 += __shfl_down_sync(0xffffffffu, s1, o);
    }
    if (lane == 0) {
        float l0 = s0 + b4[0], l1 = s1 + b4[1];
        float m = fmaxf(l0, l1);
        float lse = m + logf(expf(l0 - m) + expf(l1 - m));
        out[b*2 + 0] = l0 - lse;
        out[b*2 + 1] = l1 - lse;
    }
}

// ---------------- launch ----------------
extern "C" void kernel_launch(void* const* d_in, const int* in_sizes, int n_in,
                              void* d_out, int out_size)
{
    const float* x    = (const float*)d_in[0];
    const int*   esrc = (const int*)d_in[1];
    const int*   edst = (const int*)d_in[2];
    const float* Wc1  = (const float*)d_in[4];
    const float* bc1  = (const float*)d_in[5];
    const float* Wc2  = (const float*)d_in[6];
    const float* bc2  = (const float*)d_in[7];
    const float* Wc3  = (const float*)d_in[8];
    const float* bc3  = (const float*)d_in[9];
    const float* bn_g = (const float*)d_in[10];
    const float* bn_b = (const float*)d_in[11];
    const float* bnh_g= (const float*)d_in[12];
    const float* bnh_b= (const float*)d_in[13];
    const float* W1   = (const float*)d_in[14];
    const float* b1   = (const float*)d_in[15];
    const float* g1   = (const float*)d_in[16];
    const float* be1  = (const float*)d_in[17];
    const float* W2   = (const float*)d_in[18];
    const float* b2   = (const float*)d_in[19];
    const float* g2   = (const float*)d_in[20];
    const float* be2  = (const float*)d_in[21];
    const float* W3   = (const float*)d_in[22];
    const float* b3   = (const float*)d_in[23];
    const float* g3   = (const float*)d_in[24];
    const float* be3  = (const float*)d_in[25];
    const float* W4   = (const float*)d_in[26];
    const float* b4   = (const float*)d_in[27];
    float* out = (float*)d_out;

    void *pDinv, *pA, *pH, *pX1, *pX2, *pX3, *pZ, *pHp, *pA1, *pA2, *pA3;
    cudaGetSymbolAddress(&pDinv, g_dinv);
    cudaGetSymbolAddress(&pA,  g_A);
    cudaGetSymbolAddress(&pH,  g_h);
    cudaGetSymbolAddress(&pX1, g_xs1);
    cudaGetSymbolAddress(&pX2, g_xs2);
    cudaGetSymbolAddress(&pX3, g_xs3);
    cudaGetSymbolAddress(&pZ,  g_z);
    cudaGetSymbolAddress(&pHp, g_hpool);
    cudaGetSymbolAddress(&pA1, g_a1);
    cudaGetSymbolAddress(&pA2, g_a2);
    cudaGetSymbolAddress(&pA3, g_a3);

    // 1) degrees -> dinv
    cudaMemsetAsync(pDinv, 0, (size_t)NNODE*sizeof(float), 0);
    k_count_deg<<<(NEDGE+255)/256, 256>>>(edst);
    k_make_dinv<<<(NNODE+255)/256, 256>>>();

    // 2) dense normalized adjacency (shared by all 3 layers)
    cudaMemsetAsync(pA, 0, (size_t)BGRAPH*FN*FN*sizeof(float), 0);
    k_build_A<<<(NEDGE+255)/256, 256>>>(esrc, edst);
    k_add_self<<<(NNODE+255)/256, 256>>>();

    const long sAb = (long)FN*FN;      // per-graph adjacency stride
    const long sHb = (long)FN*CCH;     // per-graph feature stride

    // 3) GCN layer 1: h = x @ Wc1 ; xs1 = tanh(A @ h + bc1)
    mmak<0,0><<<dim3(360,1,1), 256>>>(x, Wc1, nullptr, (float*)pH,
                                      NNODE, CCH, FN, 0,0,0, 0);
    mmak<1,0><<<dim3(3,1,BGRAPH), 256>>>((const float*)pA, (const float*)pH, bc1, (float*)pX1,
                                         FN, CCH, FN, sAb, sHb, sHb, 0);
    // 4) layer 2
    mmak<0,0><<<dim3(360,1,1), 256>>>((const float*)pX1, Wc2, nullptr, (float*)pH,
                                      NNODE, CCH, CCH, 0,0,0, 0);
    mmak<1,0><<<dim3(3,1,BGRAPH), 256>>>((const float*)pA, (const float*)pH, bc2, (float*)pX2,
                                         FN, CCH, FN, sAb, sHb, sHb, 0);
    // 5) layer 3
    mmak<0,0><<<dim3(360,1,1), 256>>>((const float*)pX2, Wc3, nullptr, (float*)pH,
                                      NNODE, CCH, CCH, 0,0,0, 0);
    mmak<1,0><<<dim3(3,1,BGRAPH), 256>>>((const float*)pA, (const float*)pH, bc3, (float*)pX3,
                                         FN, CCH, FN, sAb, sHb, sHb, 0);

    // 6) z = [ BN(triu(x)) | BN(pool(xs1..3)) ]
    k_x0_bn<<<FN, 384>>>(x, bn_g, bn_b, (float*)pZ);
    k_pool<<<dim3(BGRAPH,3), CCH>>>((const float*)pX1, (const float*)pX2, (const float*)pX3, (float*)pHp);
    k_bn_pool<<<3, 128>>>((const float*)pHp, bnh_g, bnh_b, (float*)pZ);

    // 7) a1 = relu(BN(z @ W1 + b1))   (tf32 split-K, fp32 atomics)
    cudaMemsetAsync(pA1, 0, (size_t)BGRAPH*H1*sizeof(float), 0);
    mmak<0,1><<<dim3(1,4,64), 256>>>((const float*)pZ, W1, nullptr, (float*)pA1,
                                     BGRAPH, H1, D1, 0,0,0, 1024);
    k_bn_relu<<<H1, 128>>>((const float*)pA1, b1, g1, be1, (float*)pA1, H1);

    // 8) a2 = relu(BN(a1 @ W2 + b2))
    mmak<0,0><<<dim3(1,2,1), 256>>>((const float*)pA1, W2, nullptr, (float*)pA2,
                                    BGRAPH, H2, H1, 0,0,0, 0);
    k_bn_relu<<<H2, 128>>>((const float*)pA2, b2, g2, be2, (float*)pA2, H2);

    // 9) a3 = relu(BN(a2 @ W3 + b3))
    mmak<0,0><<<dim3(1,2,1), 256>>>((const float*)pA2, W3, nullptr, (float*)pA3,
                                    BGRAPH, H2, H2, 0,0,0, 0);
    k_bn_relu<<<H2, 128>>>((const float*)pA3, b3, g3, be3, (float*)pA3, H2);

    // 10) logits + log_softmax
    k_head<<<BGRAPH, 32>>>((const float*)pA3, W4, b4, out);
}